// round 6
// baseline (speedup 1.0000x reference)
#include <cuda_runtime.h>

// Problem constants (fixed by the reference)
#define B_TOT  8192
#define T_STEPS 25
#define D0     100
#define H1     100
#define H2     400
#define OUTN   784
#define BM     8                   // batch rows per block (1 row per warp... 1 per thread-row)
#define NBLK   (B_TOT / BM)        // 1024 blocks
#define NTHR   256
#define KT2    20                  // k-chunk for layer2 staging
#define KT3    20                  // k-chunk for layer3 staging

// Shared memory layout (floats):
//  sS2X : BM*H2 = 3200 (union: x tile occupies first BM*D0=800 during L1)
//  sS1  : 800, sM1 : 800, sM2 : 3200, sW : KT3*OUTN = 15680
#define OFF_S1  3200
#define OFF_M1  4000
#define OFF_M2  4800
#define OFF_W   8000
#define SMEM_FLOATS (OFF_W + KT3 * OUTN)     // 23680
#define SMEM_BYTES  (SMEM_FLOATS * 4)        // 94720

// Device scratch (allowed: __device__ globals, no allocation)
__device__ __align__(16) float g_W1T[D0 * H1];     // [k][n]
__device__ __align__(16) float g_W2T[H1 * H2];     // [k][n]
__device__ __align__(16) float g_W3T[H2 * OUTN];   // [k][n]
__device__ __align__(16) float g_m3[(size_t)B_TOT * OUTN];   // 25.7 MB, fits L2

typedef unsigned long long ull;

__device__ __forceinline__ void fma2(ull &acc, ull a, ull b) {
    asm("fma.rn.f32x2 %0, %1, %2, %0;" : "+l"(acc) : "l"(a), "l"(b));
}
__device__ __forceinline__ ull add2(ull a, ull b) {
    ull r; asm("add.rn.f32x2 %0, %1, %2;" : "=l"(r) : "l"(a), "l"(b)); return r;
}
__device__ __forceinline__ ull splat2(float s) {
    ull r; asm("mov.b64 %0, {%1, %1};" : "=l"(r) : "f"(s)); return r;
}
__device__ __forceinline__ float2 unpack2(ull v) {
    float2 f; asm("mov.b64 {%0, %1}, %2;" : "=f"(f.x), "=f"(f.y) : "l"(v)); return f;
}

// LIF with contracted membrane update (vectorized/fast-math hypothesis):
//   m' = fma(0.95, m, c) - rs   (sub exact), spike strict >
__device__ __forceinline__ void lif_update(float accv, float bv,
                                           float &m, float &spk)
{
    float v  = __fadd_rn(accv, bv);
    float c  = fmaxf(0.f, __fmul_rn(2.f, v));
    float rs = (m > 1.f) ? 1.f : 0.f;
    m = __fsub_rn(__fmaf_rn(0.95f, m, c), rs);
    spk = (m > 1.f) ? 1.f : 0.f;
}

// C[row, N] = In[row, K] * WT[K, N], strided-4 vectorized-reduction order:
//   S_L = fused fma chain over k ≡ L (mod 4), ascending
//   result = (S0 + S1) + (S2 + S3)          [pairwise faddp-style combine]
// Thread (lane, wrp): row = wrp, neuron groups n4 = lane + 32*j.
template<int NJ, int N, int K, int KT, int NACT>
__device__ __forceinline__ void gemm_layer(
    ull (&acc)[4][NJ][2],
    const float* __restrict__ gWT,   // [K][N] in global
    const float* sIn,                // [BM][K] in shared
    float* sW, int tid)
{
    const int lane = tid & 31;
    const int wrp  = tid >> 5;
    #pragma unroll 1
    for (int kc = 0; kc < K; kc += KT) {          // kc always multiple of 4
        __syncthreads();   // sW free from previous use
        {
            const float4* src = (const float4*)(gWT + kc * N);
            float4* dst = (float4*)sW;
            #pragma unroll 1
            for (int idx = tid; idx < KT * N / 4; idx += NTHR) dst[idx] = src[idx];
        }
        __syncthreads();   // chunk staged
        #pragma unroll 4
        for (int kk = 0; kk < KT; kk++) {
            ull sv = splat2(sIn[wrp * K + kc + kk]);   // warp-broadcast LDS
            const int L = kk & 3;                       // == (kc+kk) & 3
            #pragma unroll
            for (int j = 0; j < NJ; j++) {
                int n4 = lane + 32 * j;
                if (NJ * 32 > NACT) { if (n4 >= NACT) n4 = 0; }
                ulonglong2 w = *(const ulonglong2*)&sW[kk * N + n4 * 4]; // LDS.128
                fma2(acc[L][j][0], sv, w.x);
                fma2(acc[L][j][1], sv, w.y);
            }
        }
    }
    // pairwise combine into acc[0]
    #pragma unroll
    for (int j = 0; j < NJ; j++)
        #pragma unroll
        for (int p = 0; p < 2; p++) {
            ull a01 = add2(acc[0][j][p], acc[1][j][p]);
            ull a23 = add2(acc[2][j][p], acc[3][j][p]);
            acc[0][j][p] = add2(a01, a23);
        }
}

template<int NJ>
__device__ __forceinline__ void init_acc(ull (&acc)[4][NJ][2])
{
    #pragma unroll
    for (int L = 0; L < 4; L++)
        #pragma unroll
        for (int j = 0; j < NJ; j++) { acc[L][j][0] = 0ull; acc[L][j][1] = 0ull; }
}

// LIF with membranes + spikes in shared memory (layers 1,2). Row = wrp.
template<int NJ, int N, int NACT>
__device__ __forceinline__ void lif_smem(ull (&acc)[4][NJ][2],
                                         const float* __restrict__ bias,
                                         float* sM, float* sS, int tid)
{
    const int lane = tid & 31;
    const int wrp  = tid >> 5;
    #pragma unroll
    for (int j = 0; j < NJ; j++) {
        int n4 = lane + 32 * j;
        if (n4 < NACT) {
            float4 bb = *(const float4*)&bias[n4 * 4];
            float bv[4] = { bb.x, bb.y, bb.z, bb.w };
            float2 fa = unpack2(acc[0][j][0]);
            float2 fb = unpack2(acc[0][j][1]);
            float av[4] = { fa.x, fa.y, fb.x, fb.y };
            #pragma unroll
            for (int q = 0; q < 4; q++) {
                int n = n4 * 4 + q;
                float m = sM[wrp * N + n];
                float spk;
                lif_update(av[q], bv[q], m, spk);
                sM[wrp * N + n] = m;
                sS[wrp * N + n] = spk;
            }
        }
    }
}

extern "C" __global__ void __launch_bounds__(NTHR, 1)
snn_kernel(const float* __restrict__ x,
           const float* __restrict__ b1, const float* __restrict__ b2,
           const float* __restrict__ b3, float* __restrict__ out)
{
    extern __shared__ float smem[];
    float* sS2X = smem;             // s2 spikes / x tile (union)
    float* sS1  = smem + OFF_S1;
    float* sM1  = smem + OFF_M1;
    float* sM2  = smem + OFF_M2;
    float* sW   = smem + OFF_W;

    const int tid  = threadIdx.x;
    const int lane = tid & 31;
    const int wrp  = tid >> 5;
    const int row0 = blockIdx.x * BM;

    // Zero membrane state (block-private; ordered by the first sync in the loop)
    for (int i = tid; i < BM * H1; i += NTHR) sM1[i] = 0.f;
    for (int i = tid; i < BM * H2; i += NTHR) sM2[i] = 0.f;
    {
        float4 z = make_float4(0.f, 0.f, 0.f, 0.f);
        float4* m3p = (float4*)(g_m3 + (size_t)row0 * OUTN);
        for (int i = tid; i < BM * OUTN / 4; i += NTHR) m3p[i] = z;
    }

    for (int t = 0; t < T_STEPS; t++) {
        __syncthreads();   // previous-step readers of sS2X done (also orders init)

        // Stage x[:, t, :] tile into sS2X[0 : BM*D0)
        for (int i = tid; i < BM * D0; i += NTHR) {
            int rr = i / D0, k = i - rr * D0;
            sS2X[rr * D0 + k] = x[((size_t)(row0 + rr) * T_STEPS + t) * D0 + k];
        }

        // -------- Layer 1: [BM,100] x [100,100] --------
        {
            ull acc[4][1][2];
            init_acc<1>(acc);
            gemm_layer<1, H1, D0, 100, 25>(acc, g_W1T, sS2X, sW, tid);
            lif_smem<1, H1, 25>(acc, b1, sM1, sS1, tid);
        }
        // -------- Layer 2: [BM,100] x [100,400] --------
        {
            ull acc[4][4][2];
            init_acc<4>(acc);
            gemm_layer<4, H2, H1, KT2, 100>(acc, g_W2T, sS1, sW, tid);
            lif_smem<4, H2, 100>(acc, b2, sM2, sS2X, tid);
        }
        // -------- Layer 3: [BM,400] x [400,784] --------
        {
            ull acc[4][7][2];
            init_acc<7>(acc);
            gemm_layer<7, OUTN, H2, KT3, 196>(acc, g_W3T, sS2X, sW, tid);

            int row = row0 + wrp;
            #pragma unroll
            for (int j = 0; j < 7; j++) {
                int n4 = lane + 32 * j;
                if (n4 < 196) {
                    int n0 = n4 * 4;
                    float4 bb = *(const float4*)&b3[n0];
                    float bv[4] = { bb.x, bb.y, bb.z, bb.w };
                    float4 mv = *(float4*)&g_m3[(size_t)row * OUTN + n0];
                    float2 fa = unpack2(acc[0][j][0]);
                    float2 fb = unpack2(acc[0][j][1]);
                    float av[4] = { fa.x, fa.y, fb.x, fb.y };
                    float mm[4] = { mv.x, mv.y, mv.z, mv.w };
                    float sp[4];
                    #pragma unroll
                    for (int q = 0; q < 4; q++)
                        lif_update(av[q], bv[q], mm[q], sp[q]);
                    *(float4*)&g_m3[(size_t)row * OUTN + n0] =
                        make_float4(mm[0], mm[1], mm[2], mm[3]);
                    *(float4*)&out[((size_t)row * T_STEPS + t) * OUTN + n0] =
                        make_float4(sp[0], sp[1], sp[2], sp[3]);
                }
            }
        }
    }
}

// Transpose weights to k-major for coalesced staging (exact copies)
extern "C" __global__ void prep_kernel(const float* __restrict__ W1,
                                       const float* __restrict__ W2,
                                       const float* __restrict__ W3)
{
    int i = blockIdx.x * 256 + threadIdx.x;
    if (i < H1 * D0)   { int n = i / D0, k = i - n * D0; g_W1T[k * H1   + n] = W1[i]; }
    if (i < H2 * H1)   { int n = i / H1, k = i - n * H1; g_W2T[k * H2   + n] = W2[i]; }
    if (i < OUTN * H2) { int n = i / H2, k = i - n * H2; g_W3T[k * OUTN + n] = W3[i]; }
}

extern "C" void kernel_launch(void* const* d_in, const int* in_sizes, int n_in,
                              void* d_out, int out_size)
{
    const float* x  = (const float*)d_in[0];
    const float* W1 = (const float*)d_in[1];
    const float* b1 = (const float*)d_in[2];
    const float* W2 = (const float*)d_in[3];
    const float* b2 = (const float*)d_in[4];
    const float* W3 = (const float*)d_in[5];
    const float* b3 = (const float*)d_in[6];
    float* out = (float*)d_out;

    cudaFuncSetAttribute(snn_kernel,
                         cudaFuncAttributeMaxDynamicSharedMemorySize, SMEM_BYTES);

    prep_kernel<<<(OUTN * H2 + 255) / 256, 256>>>(W1, W2, W3);
    snn_kernel<<<NBLK, NTHR, SMEM_BYTES>>>(x, b1, b2, b3, out);
}

// round 8
// speedup vs baseline: 3.5943x; 3.5943x over previous
#include <cuda_runtime.h>

// Problem constants (fixed by the reference)
#define B_TOT  8192
#define T_STEPS 25
#define D0     100
#define H1     100
#define H2     400
#define OUTN   784

typedef unsigned long long ull;

// ---------------- device scratch (no allocation) ----------------
__device__ __align__(16) float g_W1T[D0 * H1];     // [k][n]
__device__ __align__(16) float g_W2T[H1 * H2];     // [k][n]
__device__ __align__(16) float g_W3T[H2 * OUTN];   // [k][n]
// packed s2 spike bitmasks: [t][row][16 words] (13 used)
__device__ unsigned g_s2mask[(size_t)T_STEPS * B_TOT * 16];

// ---------------- packed fp32x2 helpers (bitwise == scalar, proven R2≡R4) --
__device__ __forceinline__ void fma2(ull &acc, ull a, ull b) {
    asm("fma.rn.f32x2 %0, %1, %2, %0;" : "+l"(acc) : "l"(a), "l"(b));
}
__device__ __forceinline__ ull add2(ull a, ull b) {
    ull r; asm("add.rn.f32x2 %0, %1, %2;" : "=l"(r) : "l"(a), "l"(b)); return r;
}
__device__ __forceinline__ ull splat2(float s) {
    ull r; asm("mov.b64 %0, {%1, %1};" : "=l"(r) : "f"(s)); return r;
}
__device__ __forceinline__ float2 unpack2(ull v) {
    float2 f; asm("mov.b64 {%0, %1}, %2;" : "=f"(f.x), "=f"(f.y) : "l"(v)); return f;
}

// Reference-exact LIF (fma-contracted membrane update — the R6 winner):
__device__ __forceinline__ void lif_update(float accv, float bv,
                                           float &m, float &spk)
{
    float v  = __fadd_rn(accv, bv);
    float c  = fmaxf(0.f, __fmul_rn(2.f, v));
    float rs = (m > 1.f) ? 1.f : 0.f;
    m = __fsub_rn(__fmaf_rn(0.95f, m, c), rs);
    spk = (m > 1.f) ? 1.f : 0.f;
}

// =====================================================================
// Kernel A: layers 1 + 2 for all timesteps. 256 thr, 32 rows/block.
// W1T + W2T resident in SMEM; m1, m2 in registers; s2 -> packed bitmasks.
// =====================================================================
#define NTA   256
#define BMA   32
#define GRIDA (B_TOT / BMA)          // 256
// smem float offsets  (s1m: 128 words, s2m: 512 words — NO overlap)
#define A_W1   0                      // 10000 floats
#define A_W2   10000                  // 40000 floats
#define A_X    50000                  // 3200 floats
#define A_S1M  53200                  // 128 words (32 rows x 4)
#define A_S2M  53328                  // 512 words (32 rows x 16)
#define A_SMEM_FLOATS 53840
#define A_SMEM_BYTES  (A_SMEM_FLOATS * 4)    // 215360

extern "C" __global__ void __launch_bounds__(NTA, 1)
snn_l12(const float* __restrict__ x, const float* __restrict__ b1,
        const float* __restrict__ b2)
{
    extern __shared__ float sm[];
    float* sW1 = sm + A_W1;
    float* sW2 = sm + A_W2;
    float* sX  = sm + A_X;
    unsigned* s1m = (unsigned*)(sm + A_S1M);
    unsigned* s2m = (unsigned*)(sm + A_S2M);

    const int tid  = threadIdx.x;
    const int lane = tid & 31;
    const int wid  = tid >> 5;           // 0..7, warp handles rows 4w..4w+3
    const int row0 = blockIdx.x * BMA;

    // Stage weights once (k-major, prepped)
    for (int i = tid; i < D0 * H1 / 4; i += NTA)
        ((float4*)sW1)[i] = ((const float4*)g_W1T)[i];
    for (int i = tid; i < H1 * H2 / 4; i += NTA)
        ((float4*)sW2)[i] = ((const float4*)g_W2T)[i];

    // layer-1 lane mapping: n4 = lane (lane<25), neurons 4*lane..+3
    const int  n1  = (lane < 25) ? lane : 24;
    const bool l1a = (lane < 25);
    // layer-2 lane mapping: n4 = lane + 32g, g=0..2 full, g=3 only lane<4
    const bool g3 = (lane < 4);

    float4 b1v  = *(const float4*)&b1[n1 * 4];
    float4 b2v[4];
    b2v[0] = *(const float4*)&b2[lane * 4];
    b2v[1] = *(const float4*)&b2[(lane + 32) * 4];
    b2v[2] = *(const float4*)&b2[(lane + 64) * 4];
    b2v[3] = g3 ? *(const float4*)&b2[(96 + lane) * 4] : make_float4(0, 0, 0, 0);

    float m1[4][4];          // [row][q]
    float m2[4][4][4];       // [row][g][q]
    #pragma unroll
    for (int r = 0; r < 4; r++) {
        #pragma unroll
        for (int q = 0; q < 4; q++) m1[r][q] = 0.f;
        #pragma unroll
        for (int g = 0; g < 4; g++)
            #pragma unroll
            for (int q = 0; q < 4; q++) m2[r][g][q] = 0.f;
    }

    for (int t = 0; t < T_STEPS; t++) {
        __syncthreads();                       // prior-t readers done
        for (int i = tid; i < 32 * 4;  i += NTA) s1m[i] = 0u;
        for (int i = tid; i < 32 * 16; i += NTA) s2m[i] = 0u;
        for (int i = tid; i < BMA * D0; i += NTA) {
            int rr = i / D0, k = i - rr * D0;
            sX[rr * D0 + k] = x[((size_t)(row0 + rr) * T_STEPS + t) * D0 + k];
        }
        __syncthreads();

        // ---------- layer 1: dense stride-4 gemm ----------
        ull a1[4][2][4];                       // [L][pack][row]
        #pragma unroll
        for (int L = 0; L < 4; L++)
            #pragma unroll
            for (int p = 0; p < 2; p++)
                #pragma unroll
                for (int r = 0; r < 4; r++) a1[L][p][r] = 0ull;

        #pragma unroll 1
        for (int k4 = 0; k4 < 25; k4++) {
            #pragma unroll
            for (int L = 0; L < 4; L++) {
                int k = 4 * k4 + L;
                ulonglong2 w = *(const ulonglong2*)&sW1[k * H1 + n1 * 4];
                #pragma unroll
                for (int r = 0; r < 4; r++) {
                    ull sv = splat2(sX[(4 * wid + r) * D0 + k]);
                    fma2(a1[L][0][r], sv, w.x);
                    fma2(a1[L][1][r], sv, w.y);
                }
            }
        }
        if (l1a) {
            float bv[4] = { b1v.x, b1v.y, b1v.z, b1v.w };
            #pragma unroll
            for (int r = 0; r < 4; r++) {
                float2 f0 = unpack2(add2(add2(a1[0][0][r], a1[1][0][r]),
                                         add2(a1[2][0][r], a1[3][0][r])));
                float2 f1 = unpack2(add2(add2(a1[0][1][r], a1[1][1][r]),
                                         add2(a1[2][1][r], a1[3][1][r])));
                float av[4] = { f0.x, f0.y, f1.x, f1.y };
                unsigned bits = 0;
                #pragma unroll
                for (int q = 0; q < 4; q++) {
                    float spk;
                    lif_update(av[q], bv[q], m1[r][q], spk);
                    if (spk > 0.f) bits |= 1u << ((4 * lane + q) & 31);
                }
                if (bits) atomicOr(&s1m[(4 * wid + r) * 4 + (lane >> 3)], bits);
            }
        }
        __syncthreads();

        // ---------- layer 2: sparse from s1 bitmask ----------
        #pragma unroll
        for (int r = 0; r < 4; r++) {
            const int row = 4 * wid + r;
            unsigned mk[4];
            #pragma unroll
            for (int w = 0; w < 4; w++) mk[w] = s1m[row * 4 + w];
            mk[3] &= 0xFu;                     // neurons 96..99 only (defensive)

            ull a2[4][4][2];                   // [L][g][pack]
            #pragma unroll
            for (int L = 0; L < 4; L++)
                #pragma unroll
                for (int g = 0; g < 4; g++)
                    { a2[L][g][0] = 0ull; a2[L][g][1] = 0ull; }

            #pragma unroll
            for (int L = 0; L < 4; L++) {
                const unsigned pat = 0x11111111u << L;
                #pragma unroll
                for (int w = 0; w < 4; w++) {
                    unsigned m = mk[w] & pat;
                    while (m) {
                        int b = __ffs(m) - 1; m &= m - 1;
                        int k = w * 32 + b;
                        const float* wr = &sW2[k * H2];
                        ulonglong2 w0 = *(const ulonglong2*)&wr[lane * 4];
                        ulonglong2 w1 = *(const ulonglong2*)&wr[(lane + 32) * 4];
                        ulonglong2 w2 = *(const ulonglong2*)&wr[(lane + 64) * 4];
                        a2[L][0][0] = add2(a2[L][0][0], w0.x);
                        a2[L][0][1] = add2(a2[L][0][1], w0.y);
                        a2[L][1][0] = add2(a2[L][1][0], w1.x);
                        a2[L][1][1] = add2(a2[L][1][1], w1.y);
                        a2[L][2][0] = add2(a2[L][2][0], w2.x);
                        a2[L][2][1] = add2(a2[L][2][1], w2.y);
                        if (g3) {
                            ulonglong2 w3 = *(const ulonglong2*)&wr[(96 + lane) * 4];
                            a2[L][3][0] = add2(a2[L][3][0], w3.x);
                            a2[L][3][1] = add2(a2[L][3][1], w3.y);
                        }
                    }
                }
            }
            #pragma unroll
            for (int g = 0; g < 4; g++) {
                if (g < 3 || g3) {
                    float2 f0 = unpack2(add2(add2(a2[0][g][0], a2[1][g][0]),
                                             add2(a2[2][g][0], a2[3][g][0])));
                    float2 f1 = unpack2(add2(add2(a2[0][g][1], a2[1][g][1]),
                                             add2(a2[2][g][1], a2[3][g][1])));
                    float av[4] = { f0.x, f0.y, f1.x, f1.y };
                    float bv[4] = { b2v[g].x, b2v[g].y, b2v[g].z, b2v[g].w };
                    unsigned bits = 0;
                    #pragma unroll
                    for (int q = 0; q < 4; q++) {
                        float spk;
                        lif_update(av[q], bv[q], m2[r][g][q], spk);
                        if (spk > 0.f) bits |= 1u << ((4 * lane + q) & 31);
                    }
                    int n0 = 4 * (lane + 32 * g);
                    if (bits) atomicOr(&s2m[row * 16 + (n0 >> 5)], bits);
                }
            }
        }
        __syncthreads();

        // flush s2 bitmasks for this t
        for (int i = tid; i < 32 * 13; i += NTA) {
            int rr = i / 13, w = i - rr * 13;
            g_s2mask[((size_t)t * B_TOT + row0 + rr) * 16 + w] = s2m[rr * 16 + w];
        }
    }
}

// =====================================================================
// Kernel B: layer 3, sparse. 512 thr, 7 N-slices x 64 row-tiles of 128.
// W3 slice resident in SMEM (staged once); m3 in registers across t.
// =====================================================================
#define NTB    512
#define ROWS_B 128
#define NSL    112
#define NSLICES 7
#define GRIDB  (NSLICES * (B_TOT / ROWS_B))     // 448
#define B_W3   0                                 // 44800 floats
#define B_MK   44800                             // 128*13 unsigned
#define B_SMEM_FLOATS (44800 + 128 * 13)         // 46464
#define B_SMEM_BYTES  (B_SMEM_FLOATS * 4)        // 185856

extern "C" __global__ void __launch_bounds__(NTB, 1)
snn_l3(const float* __restrict__ b3, float* __restrict__ out)
{
    extern __shared__ float sm[];
    float* sW3 = sm + B_W3;
    unsigned* smk = (unsigned*)(sm + B_MK);

    const int tid  = threadIdx.x;
    const int lane = tid & 31;
    const int wid  = tid >> 5;                 // 0..15
    const int slice = blockIdx.x % NSLICES;
    const int tile  = blockIdx.x / NSLICES;    // 0..63
    const int rowbase = tile * ROWS_B;
    const int ncol0   = slice * NSL;

    // stage the W3 N-slice: [400][112]
    for (int i = tid; i < H2 * (NSL / 4); i += NTB) {
        int k = i / (NSL / 4), c = i - k * (NSL / 4);
        *(float4*)&sW3[k * NSL + c * 4] =
            *(const float4*)&g_W3T[(size_t)k * OUTN + ncol0 + c * 4];
    }

    const bool act = (lane < 28);
    const int  nl  = act ? lane : 27;
    float4 b3v = *(const float4*)&b3[ncol0 + nl * 4];
    float bv[4] = { b3v.x, b3v.y, b3v.z, b3v.w };

    float m3[8][4];                            // [ri][q], row = ri*16 + wid
    #pragma unroll
    for (int ri = 0; ri < 8; ri++)
        #pragma unroll
        for (int q = 0; q < 4; q++) m3[ri][q] = 0.f;

    for (int t = 0; t < T_STEPS; t++) {
        __syncthreads();                       // mask buffer free
        for (int i = tid; i < ROWS_B * 13; i += NTB) {
            int rr = i / 13, w = i - rr * 13;
            unsigned v = g_s2mask[((size_t)t * B_TOT + rowbase + rr) * 16 + w];
            if (w == 12) v &= 0xFFFFu;         // neurons 384..399 only (defensive)
            smk[rr * 13 + w] = v;
        }
        __syncthreads();

        #pragma unroll
        for (int ri = 0; ri < 8; ri++) {
            const int r = ri * 16 + wid;
            ull acc[4][2];
            #pragma unroll
            for (int L = 0; L < 4; L++) { acc[L][0] = 0ull; acc[L][1] = 0ull; }

            #pragma unroll
            for (int L = 0; L < 4; L++) {
                const unsigned pat = 0x11111111u << L;
                #pragma unroll 1
                for (int w = 0; w < 13; w++) {
                    unsigned m = smk[r * 13 + w] & pat;
                    while (m) {
                        int b = __ffs(m) - 1; m &= m - 1;
                        int k = w * 32 + b;
                        ulonglong2 wv = *(const ulonglong2*)&sW3[k * NSL + nl * 4];
                        acc[L][0] = add2(acc[L][0], wv.x);
                        acc[L][1] = add2(acc[L][1], wv.y);
                    }
                }
            }
            float2 f0 = unpack2(add2(add2(acc[0][0], acc[1][0]),
                                     add2(acc[2][0], acc[3][0])));
            float2 f1 = unpack2(add2(add2(acc[0][1], acc[1][1]),
                                     add2(acc[2][1], acc[3][1])));
            float av[4] = { f0.x, f0.y, f1.x, f1.y };
            float sp[4];
            #pragma unroll
            for (int q = 0; q < 4; q++)
                lif_update(av[q], bv[q], m3[ri][q], sp[q]);
            if (act)
                *(float4*)&out[((size_t)(rowbase + r) * T_STEPS + t) * OUTN
                               + ncol0 + nl * 4]
                    = make_float4(sp[0], sp[1], sp[2], sp[3]);
        }
    }
}

// ---------------- prep: k-major weight transposes ----------------
extern "C" __global__ void prep_kernel(const float* __restrict__ W1,
                                       const float* __restrict__ W2,
                                       const float* __restrict__ W3)
{
    int i = blockIdx.x * 256 + threadIdx.x;
    if (i < H1 * D0)   { int n = i / D0, k = i - n * D0; g_W1T[k * H1   + n] = W1[i]; }
    if (i < H2 * H1)   { int n = i / H1, k = i - n * H1; g_W2T[k * H2   + n] = W2[i]; }
    if (i < OUTN * H2) { int n = i / H2, k = i - n * H2; g_W3T[k * OUTN + n] = W3[i]; }
}

extern "C" void kernel_launch(void* const* d_in, const int* in_sizes, int n_in,
                              void* d_out, int out_size)
{
    const float* x  = (const float*)d_in[0];
    const float* W1 = (const float*)d_in[1];
    const float* b1 = (const float*)d_in[2];
    const float* W2 = (const float*)d_in[3];
    const float* b2 = (const float*)d_in[4];
    const float* W3 = (const float*)d_in[5];
    const float* b3 = (const float*)d_in[6];
    float* out = (float*)d_out;

    cudaFuncSetAttribute(snn_l12,
                         cudaFuncAttributeMaxDynamicSharedMemorySize, A_SMEM_BYTES);
    cudaFuncSetAttribute(snn_l3,
                         cudaFuncAttributeMaxDynamicSharedMemorySize, B_SMEM_BYTES);

    prep_kernel<<<(OUTN * H2 + 255) / 256, 256>>>(W1, W2, W3);
    snn_l12<<<GRIDA, NTA, A_SMEM_BYTES>>>(x, b1, b2);
    snn_l3<<<GRIDB, NTB, B_SMEM_BYTES>>>(b3, out);
}